// round 16
// baseline (speedup 1.0000x reference)
#include <cuda_runtime.h>
#include <cstddef>

#define B_ 256
#define S_ 200
#define E_ 512
#define H_ 512

// ---- scratch (no allocations allowed) ----
__device__ float g_P[(size_t)B_ * S_ * H_];   // 104 MB: P[t][b][h]
__device__ float g_pool[B_ * H_];             // time-mean of h

typedef unsigned long long u64;

__device__ __forceinline__ void fma2(u64 &c, u64 a, u64 b) {
    asm("fma.rn.f32x2 %0, %1, %2, %3;" : "=l"(c) : "l"(a), "l"(b), "l"(c));
}
__device__ __forceinline__ u64 splat2(float a) {
    u64 r; asm("mov.b64 %0, {%1, %1};" : "=l"(r) : "f"(a)); return r;
}
__device__ __forceinline__ float2 u2f(u64 v) {
    float2 r; asm("mov.b64 {%0, %1}, %2;" : "=f"(r.x), "=f"(r.y) : "l"(v)); return r;
}
__device__ __forceinline__ u64 packP(float lo) {  // (P, 0) initial partials
    u64 r; float z = 0.0f;
    asm("mov.b64 %0, {%1, %2};" : "=l"(r) : "f"(lo), "f"(z));
    return r;
}
__device__ __forceinline__ unsigned smem_u32(const void* p) {
    unsigned a;
    asm("{ .reg .u64 t; cvta.to.shared.u64 t, %1; cvt.u32.u64 %0, t; }" : "=r"(a) : "l"(p));
    return a;
}

// ============================================================================
// Kernel A: P = gather(emb, x) @ Wxh + (bxh + bhh)   (unchanged from R5)
// ============================================================================
#define PAST 36
#define PC_SMEM ((2 * 64 * PAST + 2 * 32 * 128) * 4)  // 51200 B

__global__ __launch_bounds__(256, 2) void precompute_kernel(
    const int* __restrict__ x, const float* __restrict__ emb,
    const float* __restrict__ Wxh, const float* __restrict__ bxh,
    const float* __restrict__ bhh)
{
    extern __shared__ float psm[];
    float* AsB = psm;                    // [2][64][PAST]
    float* WsB = psm + 2 * 64 * PAST;    // [2][32][128]

    const int n0 = blockIdx.x * 128;
    const int m0 = blockIdx.y * 64;
    const int t  = threadIdx.x;
    const int w  = t >> 5, l = t & 31;
    const int row0 = w * 8;
    const int c4 = 4 * l;

    const int arow  = t >> 3;
    const int aslot = (t & 7) * 4;
    const size_t e0 = (size_t)x[m0 + arow] * E_;
    const size_t e1 = (size_t)x[m0 + arow + 32] * E_;
    const int wrow = t >> 5;
    const int wcol = (t & 31) * 4;

    u64 acc[8][2];
#pragma unroll
    for (int i = 0; i < 8; i++) { acc[i][0] = 0ull; acc[i][1] = 0ull; }

    float4 pa0, pa1, pw0, pw1, pw2, pw3;
    pa0 = *(const float4*)&emb[e0 + aslot];
    pa1 = *(const float4*)&emb[e1 + aslot];
    pw0 = *(const float4*)&Wxh[(size_t)(0  + wrow) * H_ + n0 + wcol];
    pw1 = *(const float4*)&Wxh[(size_t)(8  + wrow) * H_ + n0 + wcol];
    pw2 = *(const float4*)&Wxh[(size_t)(16 + wrow) * H_ + n0 + wcol];
    pw3 = *(const float4*)&Wxh[(size_t)(24 + wrow) * H_ + n0 + wcol];
    *(float4*)&AsB[arow * PAST + aslot]        = pa0;
    *(float4*)&AsB[(arow + 32) * PAST + aslot] = pa1;
    *(float4*)&WsB[(0  + wrow) * 128 + wcol] = pw0;
    *(float4*)&WsB[(8  + wrow) * 128 + wcol] = pw1;
    *(float4*)&WsB[(16 + wrow) * 128 + wcol] = pw2;
    *(float4*)&WsB[(24 + wrow) * 128 + wcol] = pw3;
    __syncthreads();

#pragma unroll 1
    for (int ch = 0; ch < 16; ch++) {
        if (ch < 15) {
            const int kn = (ch + 1) * 32;
            pa0 = *(const float4*)&emb[e0 + kn + aslot];
            pa1 = *(const float4*)&emb[e1 + kn + aslot];
            pw0 = *(const float4*)&Wxh[(size_t)(kn + wrow) * H_ + n0 + wcol];
            pw1 = *(const float4*)&Wxh[(size_t)(kn + 8  + wrow) * H_ + n0 + wcol];
            pw2 = *(const float4*)&Wxh[(size_t)(kn + 16 + wrow) * H_ + n0 + wcol];
            pw3 = *(const float4*)&Wxh[(size_t)(kn + 24 + wrow) * H_ + n0 + wcol];
        }
        const float* Ab = AsB + (ch & 1) * (64 * PAST);
        const float* Wb = WsB + (ch & 1) * (32 * 128);

#pragma unroll
        for (int kg = 0; kg < 8; kg++) {
            float4 a0 = *(const float4*)&Ab[(row0 + 0) * PAST + kg * 4];
            float4 a1 = *(const float4*)&Ab[(row0 + 1) * PAST + kg * 4];
            float4 a2 = *(const float4*)&Ab[(row0 + 2) * PAST + kg * 4];
            float4 a3 = *(const float4*)&Ab[(row0 + 3) * PAST + kg * 4];
            float4 a4 = *(const float4*)&Ab[(row0 + 4) * PAST + kg * 4];
            float4 a5 = *(const float4*)&Ab[(row0 + 5) * PAST + kg * 4];
            float4 a6 = *(const float4*)&Ab[(row0 + 6) * PAST + kg * 4];
            float4 a7 = *(const float4*)&Ab[(row0 + 7) * PAST + kg * 4];
#define PKJ(j, comp) {                                              \
            const u64* wp = (const u64*)&Wb[(kg * 4 + (j)) * 128 + c4]; \
            u64 w01 = wp[0], w23 = wp[1];                           \
            fma2(acc[0][0], splat2(a0.comp), w01); fma2(acc[0][1], splat2(a0.comp), w23); \
            fma2(acc[1][0], splat2(a1.comp), w01); fma2(acc[1][1], splat2(a1.comp), w23); \
            fma2(acc[2][0], splat2(a2.comp), w01); fma2(acc[2][1], splat2(a2.comp), w23); \
            fma2(acc[3][0], splat2(a3.comp), w01); fma2(acc[3][1], splat2(a3.comp), w23); \
            fma2(acc[4][0], splat2(a4.comp), w01); fma2(acc[4][1], splat2(a4.comp), w23); \
            fma2(acc[5][0], splat2(a5.comp), w01); fma2(acc[5][1], splat2(a5.comp), w23); \
            fma2(acc[6][0], splat2(a6.comp), w01); fma2(acc[6][1], splat2(a6.comp), w23); \
            fma2(acc[7][0], splat2(a7.comp), w01); fma2(acc[7][1], splat2(a7.comp), w23); }
            PKJ(0, x) PKJ(1, y) PKJ(2, z) PKJ(3, w)
#undef PKJ
        }

        if (ch < 15) {
            float* An = AsB + ((ch + 1) & 1) * (64 * PAST);
            float* Wn = WsB + ((ch + 1) & 1) * (32 * 128);
            *(float4*)&An[arow * PAST + aslot]        = pa0;
            *(float4*)&An[(arow + 32) * PAST + aslot] = pa1;
            *(float4*)&Wn[(0  + wrow) * 128 + wcol] = pw0;
            *(float4*)&Wn[(8  + wrow) * 128 + wcol] = pw1;
            *(float4*)&Wn[(16 + wrow) * 128 + wcol] = pw2;
            *(float4*)&Wn[(24 + wrow) * 128 + wcol] = pw3;
            __syncthreads();
        }
    }

    float4 bxv = *(const float4*)&bxh[n0 + c4];
    float4 bhv = *(const float4*)&bhh[n0 + c4];
    const float b0 = bxv.x + bhv.x, b1 = bxv.y + bhv.y;
    const float b2 = bxv.z + bhv.z, b3 = bxv.w + bhv.w;
#pragma unroll
    for (int i = 0; i < 8; i++) {
        float2 v0 = u2f(acc[i][0]);
        float2 v1 = u2f(acc[i][1]);
        float4 o; o.x = v0.x + b0; o.y = v0.y + b1; o.z = v1.x + b2; o.w = v1.y + b3;
        int m = m0 + row0 + i;
        int bb = m / S_;
        int tt = m - bb * S_;
        *(float4*)&g_P[((size_t)tt * B_ + bb) * H_ + n0 + c4] = o;
    }
}

// ============================================================================
// Kernel B: persistent RNN — DSMEM pull exchange + mbarrier (no global h,
// no cluster.sync, no spin). 128 CTAs = 16 clusters of 8; cluster = M-group,
// rank r owns cols 64r..64r+63. Whh slice k-major 132KB stationary in smem.
// Per step: compute (k-pair FFMA2, splat-free, 4096cyc floor) → STS own 4KB
// h slice to own double-buffered Hb → t0 arrives (release.cluster) at all 8
// CTAs' phase mbarrier → all threads try_wait (acquire.cluster) → warp w
// pulls peer w's slice via ld.shared::cluster into As.
// ============================================================================
#define CL 8
#define WST 516
#define AST 516
#define HST 68
#define RNN_SMEM ((64 * WST + 16 * AST + 2 * 16 * HST) * 4 + 64)

__global__ __launch_bounds__(256, 1) __cluster_dims__(CL, 1, 1)
void rnn_kernel(const float* __restrict__ Whh)
{
    extern __shared__ float sm[];
    float* Wk = sm;                      // [64 cols][WST k]  (k-major)
    float* As = sm + 64 * WST;           // [16 rows][AST]  full h staging
    float* Hb = As + 16 * AST;           // [2][16][HST]  own 64-col slice
    const unsigned mbar = smem_u32(Hb + 2 * 16 * HST);  // 2 x 8B mbarriers

    unsigned rank;
    asm("mov.u32 %0, %%cluster_ctarank;" : "=r"(rank));
    const int mg = blockIdx.x >> 3;
    const int m0 = mg * 16;
    const int n0 = (int)rank * 64;
    const int t  = threadIdx.x;
    const int w  = t >> 5, l = t & 31;
    const int rp  = l & 7;               // rows rp, rp+8
    const int cpl = l >> 3;              // 0..3
    const int cA  = 8 * w + 2 * cpl;     // local cols cA, cA+1

    // ---- init: Wk[c][k] = Whh[k][n0+c] (coalesced global reads)
#pragma unroll 4
    for (int rep = 0; rep < 128; rep++) {
        int idx = rep * 256 + t;
        int k = idx >> 6, c = idx & 63;
        Wk[c * WST + k] = Whh[(size_t)k * H_ + n0 + c];
    }
    for (int i = t; i < 16 * AST; i += 256) As[i] = 0.0f;       // h(0) = 0
    for (int i = t; i < 2 * 16 * HST; i += 256) Hb[i] = 0.0f;
    if (t == 0) {
        asm volatile("mbarrier.init.shared.b64 [%0], 8;" :: "r"(mbar) : "memory");
        asm volatile("mbarrier.init.shared.b64 [%0], 8;" :: "r"(mbar + 8) : "memory");
    }
    __syncthreads();
    // one-time cluster barrier: mbarrier inits visible before any arrives
    asm volatile("barrier.cluster.arrive.aligned;" ::: "memory");
    asm volatile("barrier.cluster.wait.aligned;"   ::: "memory");

    // ---- stage mapping: warp w pulls peer w's slice
    const unsigned hb_local = smem_u32(Hb);
    unsigned peer_hb;
    asm("mapa.shared::cluster.u32 %0, %1, %2;" : "=r"(peer_hb) : "r"(hb_local), "r"(w));
    const int srow = l >> 1;
    const int scol = (l & 1) * 32;
    const unsigned src0 = peer_hb + (unsigned)(srow * HST + scol) * 4u;
    float* const dstp = &As[srow * AST + 64 * w + scol];

    // ---- compute pointers
    const float* apA = &As[rp * AST];
    const float* apB = &As[(rp + 8) * AST];
    const float* wpA = &Wk[cA * WST];
    const float* wpB = &Wk[(cA + 1) * WST];

    const size_t pstride = (size_t)B_ * H_;
    const size_t pbA = (size_t)(m0 + rp) * H_ + n0 + cA;
    const size_t pbB = (size_t)(m0 + rp + 8) * H_ + n0 + cA;

    float4 ps = {0, 0, 0, 0};   // pool sums: (rA,cA),(rA,cA+1),(rB,cA),(rB,cA+1)
    int par0 = 0, par1 = 0;

    for (int step = 0; step < S_; step++) {
        // wait for all 8 producers of h(step) (skip step 0: zeros pre-staged)
        if (step > 0) {
            const unsigned bad = mbar + (unsigned)(step & 1) * 8u;
            const unsigned ph = (step & 1) ? par1 : par0;
            asm volatile(
                "{\n\t.reg .pred P1;\n"
                "W%=:\n\t"
                "mbarrier.try_wait.parity.acquire.cluster.shared::cta.b64 P1, [%0], %1, 0x989680;\n\t"
                "@P1 bra D%=;\n\t"
                "bra W%=;\n"
                "D%=:\n\t}"
                :: "r"(bad), "r"(ph) : "memory");
            if (step & 1) par1 ^= 1; else par0 ^= 1;
        }

        // P loads for this step (independent; latency hidden by staging)
        u64 pPA = *(const u64*)&g_P[pbA + (size_t)step * pstride];
        u64 pPB = *(const u64*)&g_P[pbB + (size_t)step * pstride];

        if (step > 0) {
            // pull peer w's 16x64 slice of h(step) from Hb[step&1]
            const unsigned src = src0 + (unsigned)((step & 1) * 16 * HST) * 4u;
#pragma unroll
            for (int i = 0; i < 8; i++) {
                unsigned r0, r1, r2, r3;
                asm volatile("ld.shared::cluster.v4.b32 {%0,%1,%2,%3}, [%4];"
                    : "=r"(r0), "=r"(r1), "=r"(r2), "=r"(r3)
                    : "r"(src + 16u * i) : "memory");
                float4 v;
                v.x = __uint_as_float(r0); v.y = __uint_as_float(r1);
                v.z = __uint_as_float(r2); v.w = __uint_as_float(r3);
                *(float4*)(dstp + 4 * i) = v;
            }
            __syncthreads();
        }

        // ---- GEMM: k-pair partials, no splats. 12 inst / 4k per thread.
        float2 pA = u2f(pPA), pB = u2f(pPB);
        u64 a00 = packP(pA.x), a01 = packP(pA.y);
        u64 a10 = packP(pB.x), a11 = packP(pB.y);
#pragma unroll 4
        for (int k = 0; k < H_; k += 4) {
            ulonglong2 Aa = *(const ulonglong2*)(apA + k);
            ulonglong2 Ab = *(const ulonglong2*)(apB + k);
            ulonglong2 Wa = *(const ulonglong2*)(wpA + k);
            ulonglong2 Wb = *(const ulonglong2*)(wpB + k);
            fma2(a00, Aa.x, Wa.x); fma2(a00, Aa.y, Wa.y);
            fma2(a01, Aa.x, Wb.x); fma2(a01, Aa.y, Wb.y);
            fma2(a10, Ab.x, Wa.x); fma2(a10, Ab.y, Wa.y);
            fma2(a11, Ab.x, Wb.x); fma2(a11, Ab.y, Wb.y);
        }
        float2 s00 = u2f(a00), s01 = u2f(a01), s10 = u2f(a10), s11 = u2f(a11);
        float v00 = fmaxf(s00.x + s00.y, 0.0f);
        float v01 = fmaxf(s01.x + s01.y, 0.0f);
        float v10 = fmaxf(s10.x + s10.y, 0.0f);
        float v11 = fmaxf(s11.x + s11.y, 0.0f);
        ps.x += v00; ps.y += v01; ps.z += v10; ps.w += v11;

        if (step + 1 < S_) {
            // publish own slice of h(step+1) into Hb[(step+1)&1]
            float* hb = Hb + ((step + 1) & 1) * 16 * HST;
            float2 o;
            o.x = v00; o.y = v01; *(float2*)&hb[rp * HST + cA] = o;
            o.x = v10; o.y = v11; *(float2*)&hb[(rp + 8) * HST + cA] = o;
            __syncthreads();    // all STS done + all As reads done
            if (t == 0) {
                const unsigned boff = (unsigned)((step + 1) & 1) * 8u;
#pragma unroll
                for (int r = 0; r < CL; r++) {
                    unsigned ra;
                    asm("mapa.shared::cluster.u32 %0, %1, %2;"
                        : "=r"(ra) : "r"(mbar + boff), "r"(r));
                    asm volatile(
                        "mbarrier.arrive.release.cluster.shared::cluster.b64 _, [%0];"
                        :: "r"(ra) : "memory");
                }
            }
        }
    }

    const float inv = 1.0f / (float)S_;
    float2 q;
    q.x = ps.x * inv; q.y = ps.y * inv; *(float2*)&g_pool[pbA] = q;
    q.x = ps.z * inv; q.y = ps.w * inv; *(float2*)&g_pool[pbB] = q;
}

// ============================================================================
// Kernel C: out = pooled @ Wfc + bfc
// ============================================================================
__global__ __launch_bounds__(128) void fc_kernel(const float* __restrict__ Wfc,
                                                 const float* __restrict__ bfc,
                                                 float* __restrict__ out)
{
    const int b = blockIdx.x;
    const int t = threadIdx.x;
    float s0 = 0, s1 = 0, s2 = 0, s3 = 0;
    const float* pr = &g_pool[(size_t)b * H_];
    for (int k = t; k < H_; k += 128) {
        float v = pr[k];
        float4 wv = *(const float4*)&Wfc[k * 4];
        s0 += v * wv.x; s1 += v * wv.y; s2 += v * wv.z; s3 += v * wv.w;
    }
#pragma unroll
    for (int o = 16; o > 0; o >>= 1) {
        s0 += __shfl_down_sync(0xffffffffu, s0, o);
        s1 += __shfl_down_sync(0xffffffffu, s1, o);
        s2 += __shfl_down_sync(0xffffffffu, s2, o);
        s3 += __shfl_down_sync(0xffffffffu, s3, o);
    }
    __shared__ float red[4][4];
    if ((t & 31) == 0) {
        int wrp = t >> 5;
        red[wrp][0] = s0; red[wrp][1] = s1; red[wrp][2] = s2; red[wrp][3] = s3;
    }
    __syncthreads();
    if (t < 4) {
        out[b * 4 + t] = red[0][t] + red[1][t] + red[2][t] + red[3][t] + bfc[t];
    }
}

// ============================================================================
extern "C" void kernel_launch(void* const* d_in, const int* in_sizes, int n_in,
                              void* d_out, int out_size)
{
    const int*   x   = (const int*)d_in[0];
    const float* emb = (const float*)d_in[1];
    const float* Wxh = (const float*)d_in[2];
    const float* bxh = (const float*)d_in[3];
    const float* Whh = (const float*)d_in[4];
    const float* bhh = (const float*)d_in[5];
    const float* Wfc = (const float*)d_in[6];
    const float* bfc = (const float*)d_in[7];
    float* out = (float*)d_out;

    cudaFuncSetAttribute(precompute_kernel, cudaFuncAttributeMaxDynamicSharedMemorySize, PC_SMEM);
    cudaFuncSetAttribute(rnn_kernel, cudaFuncAttributeMaxDynamicSharedMemorySize, RNN_SMEM);

    precompute_kernel<<<dim3(4, 800), 256, PC_SMEM>>>(x, emb, Wxh, bxh, bhh);
    rnn_kernel<<<128, 256, RNN_SMEM>>>(Whh);
    fc_kernel<<<B_, 128>>>(Wfc, bfc, out);
}

// round 17
// speedup vs baseline: 2.2439x; 2.2439x over previous
#include <cuda_runtime.h>
#include <cstddef>

#define B_ 256
#define S_ 200
#define E_ 512
#define H_ 512

// ---- scratch (no allocations allowed) ----
__device__ float g_P[(size_t)B_ * S_ * H_];   // 104 MB: P[t][b][h]
__device__ float g_h[2][B_ * H_];             // double-buffered hidden state
__device__ float g_pool[B_ * H_];             // time-mean of h
__device__ unsigned int g_bars[16];           // per-M-group barrier counters

typedef unsigned long long u64;

__device__ __forceinline__ void fma2(u64 &c, u64 a, u64 b) {
    asm("fma.rn.f32x2 %0, %1, %2, %3;" : "=l"(c) : "l"(a), "l"(b), "l"(c));
}
__device__ __forceinline__ u64 splat2(float a) {
    u64 r; asm("mov.b64 %0, {%1, %1};" : "=l"(r) : "f"(a)); return r;
}
__device__ __forceinline__ float2 u2f(u64 v) {
    float2 r; asm("mov.b64 {%0, %1}, %2;" : "=f"(r.x), "=f"(r.y) : "l"(v)); return r;
}
__device__ __forceinline__ u64 packP(float lo) {  // (P, 0) initial partials
    u64 r; float z = 0.0f;
    asm("mov.b64 %0, {%1, %2};" : "=l"(r) : "f"(lo), "f"(z));
    return r;
}

// ============================================================================
// Kernel A: P = gather(emb, x) @ Wxh + (bxh + bhh)   (unchanged from R5)
// ============================================================================
#define PAST 36
#define PC_SMEM ((2 * 64 * PAST + 2 * 32 * 128) * 4)  // 51200 B

__global__ __launch_bounds__(256, 2) void precompute_kernel(
    const int* __restrict__ x, const float* __restrict__ emb,
    const float* __restrict__ Wxh, const float* __restrict__ bxh,
    const float* __restrict__ bhh)
{
    extern __shared__ float psm[];
    float* AsB = psm;                    // [2][64][PAST]
    float* WsB = psm + 2 * 64 * PAST;    // [2][32][128]

    const int n0 = blockIdx.x * 128;
    const int m0 = blockIdx.y * 64;
    const int t  = threadIdx.x;
    const int w  = t >> 5, l = t & 31;
    const int row0 = w * 8;
    const int c4 = 4 * l;

    const int arow  = t >> 3;
    const int aslot = (t & 7) * 4;
    const size_t e0 = (size_t)x[m0 + arow] * E_;
    const size_t e1 = (size_t)x[m0 + arow + 32] * E_;
    const int wrow = t >> 5;
    const int wcol = (t & 31) * 4;

    u64 acc[8][2];
#pragma unroll
    for (int i = 0; i < 8; i++) { acc[i][0] = 0ull; acc[i][1] = 0ull; }

    float4 pa0, pa1, pw0, pw1, pw2, pw3;
    pa0 = *(const float4*)&emb[e0 + aslot];
    pa1 = *(const float4*)&emb[e1 + aslot];
    pw0 = *(const float4*)&Wxh[(size_t)(0  + wrow) * H_ + n0 + wcol];
    pw1 = *(const float4*)&Wxh[(size_t)(8  + wrow) * H_ + n0 + wcol];
    pw2 = *(const float4*)&Wxh[(size_t)(16 + wrow) * H_ + n0 + wcol];
    pw3 = *(const float4*)&Wxh[(size_t)(24 + wrow) * H_ + n0 + wcol];
    *(float4*)&AsB[arow * PAST + aslot]        = pa0;
    *(float4*)&AsB[(arow + 32) * PAST + aslot] = pa1;
    *(float4*)&WsB[(0  + wrow) * 128 + wcol] = pw0;
    *(float4*)&WsB[(8  + wrow) * 128 + wcol] = pw1;
    *(float4*)&WsB[(16 + wrow) * 128 + wcol] = pw2;
    *(float4*)&WsB[(24 + wrow) * 128 + wcol] = pw3;
    __syncthreads();

#pragma unroll 1
    for (int ch = 0; ch < 16; ch++) {
        if (ch < 15) {
            const int kn = (ch + 1) * 32;
            pa0 = *(const float4*)&emb[e0 + kn + aslot];
            pa1 = *(const float4*)&emb[e1 + kn + aslot];
            pw0 = *(const float4*)&Wxh[(size_t)(kn + wrow) * H_ + n0 + wcol];
            pw1 = *(const float4*)&Wxh[(size_t)(kn + 8  + wrow) * H_ + n0 + wcol];
            pw2 = *(const float4*)&Wxh[(size_t)(kn + 16 + wrow) * H_ + n0 + wcol];
            pw3 = *(const float4*)&Wxh[(size_t)(kn + 24 + wrow) * H_ + n0 + wcol];
        }
        const float* Ab = AsB + (ch & 1) * (64 * PAST);
        const float* Wb = WsB + (ch & 1) * (32 * 128);

#pragma unroll
        for (int kg = 0; kg < 8; kg++) {
            float4 a0 = *(const float4*)&Ab[(row0 + 0) * PAST + kg * 4];
            float4 a1 = *(const float4*)&Ab[(row0 + 1) * PAST + kg * 4];
            float4 a2 = *(const float4*)&Ab[(row0 + 2) * PAST + kg * 4];
            float4 a3 = *(const float4*)&Ab[(row0 + 3) * PAST + kg * 4];
            float4 a4 = *(const float4*)&Ab[(row0 + 4) * PAST + kg * 4];
            float4 a5 = *(const float4*)&Ab[(row0 + 5) * PAST + kg * 4];
            float4 a6 = *(const float4*)&Ab[(row0 + 6) * PAST + kg * 4];
            float4 a7 = *(const float4*)&Ab[(row0 + 7) * PAST + kg * 4];
#define PKJ(j, comp) {                                              \
            const u64* wp = (const u64*)&Wb[(kg * 4 + (j)) * 128 + c4]; \
            u64 w01 = wp[0], w23 = wp[1];                           \
            fma2(acc[0][0], splat2(a0.comp), w01); fma2(acc[0][1], splat2(a0.comp), w23); \
            fma2(acc[1][0], splat2(a1.comp), w01); fma2(acc[1][1], splat2(a1.comp), w23); \
            fma2(acc[2][0], splat2(a2.comp), w01); fma2(acc[2][1], splat2(a2.comp), w23); \
            fma2(acc[3][0], splat2(a3.comp), w01); fma2(acc[3][1], splat2(a3.comp), w23); \
            fma2(acc[4][0], splat2(a4.comp), w01); fma2(acc[4][1], splat2(a4.comp), w23); \
            fma2(acc[5][0], splat2(a5.comp), w01); fma2(acc[5][1], splat2(a5.comp), w23); \
            fma2(acc[6][0], splat2(a6.comp), w01); fma2(acc[6][1], splat2(a6.comp), w23); \
            fma2(acc[7][0], splat2(a7.comp), w01); fma2(acc[7][1], splat2(a7.comp), w23); }
            PKJ(0, x) PKJ(1, y) PKJ(2, z) PKJ(3, w)
#undef PKJ
        }

        if (ch < 15) {
            float* An = AsB + ((ch + 1) & 1) * (64 * PAST);
            float* Wn = WsB + ((ch + 1) & 1) * (32 * 128);
            *(float4*)&An[arow * PAST + aslot]        = pa0;
            *(float4*)&An[(arow + 32) * PAST + aslot] = pa1;
            *(float4*)&Wn[(0  + wrow) * 128 + wcol] = pw0;
            *(float4*)&Wn[(8  + wrow) * 128 + wcol] = pw1;
            *(float4*)&Wn[(16 + wrow) * 128 + wcol] = pw2;
            *(float4*)&Wn[(24 + wrow) * 128 + wcol] = pw3;
            __syncthreads();
        }
    }

    float4 bxv = *(const float4*)&bxh[n0 + c4];
    float4 bhv = *(const float4*)&bhh[n0 + c4];
    const float b0 = bxv.x + bhv.x, b1 = bxv.y + bhv.y;
    const float b2 = bxv.z + bhv.z, b3 = bxv.w + bhv.w;
#pragma unroll
    for (int i = 0; i < 8; i++) {
        float2 v0 = u2f(acc[i][0]);
        float2 v1 = u2f(acc[i][1]);
        float4 o; o.x = v0.x + b0; o.y = v0.y + b1; o.z = v1.x + b2; o.w = v1.y + b3;
        int m = m0 + row0 + i;
        int bb = m / S_;
        int tt = m - bb * S_;
        *(float4*)&g_P[((size_t)tt * B_ + bb) * H_ + n0 + c4] = o;
    }
}

// ============================================================================
// Kernel B: persistent RNN — R5 exchange frame + R16 splat-free compute.
// 128 CTAs = 16 M-groups x 8 ranks (64 cols). 256 threads (2 warps/SMSP).
// Whh k-major in smem: Wk[c][k] (132KB). Compute: k-pair partial sums in
// f32x2 lanes — NO splat MOVs; per thread per 4k: 4 LDS.128 + 8 FFMA2.
// Thread = 2 rows (rp, rp+8) x 2 cols (cA, cA+1). Exchange: global h double
// buffer + per-M-group red/spin barrier (proven R5 structure), P prefetched
// before the spin.
// ============================================================================
#define WST 516
#define AST 516
#define RNN_SMEM ((64 * WST + 16 * AST) * 4)  // 132096 + 33024 = 165120 B

__global__ __launch_bounds__(256, 1) void rnn_kernel(const float* __restrict__ Whh)
{
    extern __shared__ float sm[];
    float* Wk = sm;               // [64 cols][WST] k-major Whh slice
    float* As = sm + 64 * WST;    // [16 rows][AST] current h

    const int cta  = blockIdx.x;
    const int mg   = cta >> 3;
    const int rank = cta & 7;
    const int m0   = mg * 16;
    const int n0   = rank * 64;
    const int t    = threadIdx.x;
    const int w    = t >> 5, l = t & 31;
    const int rp   = l & 7;              // rows rp, rp+8
    const int cA   = 8 * w + 2 * (l >> 3);  // local cols cA, cA+1

    // ---- Wk[c][k] = Whh[k][n0+c]  (coalesced LDG; one-time scattered STS)
#pragma unroll 4
    for (int rep = 0; rep < 128; rep++) {
        int idx = rep * 256 + t;
        int k = idx >> 6, c = idx & 63;
        Wk[c * WST + k] = Whh[(size_t)k * H_ + n0 + c];
    }
    __syncthreads();

    float4 ps = {0, 0, 0, 0};

    const size_t pstride = (size_t)B_ * H_;
    const size_t pbA = (size_t)(m0 + rp) * H_ + n0 + cA;
    const size_t pbB = (size_t)(m0 + rp + 8) * H_ + n0 + cA;
    u64 pPA = *(const u64*)&g_P[pbA];
    u64 pPB = *(const u64*)&g_P[pbB];

    const float* apA = &As[rp * AST];
    const float* apB = &As[(rp + 8) * AST];
    const float* wpA = &Wk[cA * WST];
    const float* wpB = &Wk[(cA + 1) * WST];

    unsigned* bar = &g_bars[mg];
    int cur = 0;
    for (int step = 0; step < S_; step++) {
        // stage h(step) rows m0..m0+15 (2048 float4 / 256 thr = 8 reps)
        const float* hsrc = g_h[cur];
#pragma unroll
        for (int rep = 0; rep < 8; rep++) {
            int i4   = rep * 256 + t;
            int arow = i4 >> 7;
            int k4   = (i4 & 127) * 4;
            *(float4*)&As[arow * AST + k4] =
                *(const float4*)&hsrc[(size_t)(m0 + arow) * H_ + k4];
        }
        __syncthreads();

        // ---- GEMM: k-pair partials, splat-free (12 slots / 4k / thread)
        float2 pA = u2f(pPA), pB = u2f(pPB);
        u64 a00 = packP(pA.x), a01 = packP(pA.y);
        u64 a10 = packP(pB.x), a11 = packP(pB.y);
#pragma unroll 4
        for (int k = 0; k < H_; k += 4) {
            ulonglong2 Aa = *(const ulonglong2*)(apA + k);
            ulonglong2 Ab = *(const ulonglong2*)(apB + k);
            ulonglong2 Wa = *(const ulonglong2*)(wpA + k);
            ulonglong2 Wb = *(const ulonglong2*)(wpB + k);
            fma2(a00, Aa.x, Wa.x); fma2(a00, Aa.y, Wa.y);
            fma2(a01, Aa.x, Wb.x); fma2(a01, Aa.y, Wb.y);
            fma2(a10, Ab.x, Wa.x); fma2(a10, Ab.y, Wa.y);
            fma2(a11, Ab.x, Wb.x); fma2(a11, Ab.y, Wb.y);
        }
        float2 s00 = u2f(a00), s01 = u2f(a01), s10 = u2f(a10), s11 = u2f(a11);
        float v00 = fmaxf(s00.x + s00.y, 0.0f);
        float v01 = fmaxf(s01.x + s01.y, 0.0f);
        float v10 = fmaxf(s10.x + s10.y, 0.0f);
        float v11 = fmaxf(s11.x + s11.y, 0.0f);
        ps.x += v00; ps.y += v01; ps.z += v10; ps.w += v11;

        // publish own 16x64 slice of h(step+1)
        float* hdst = g_h[cur ^ 1];
        float2 o;
        o.x = v00; o.y = v01; *(float2*)&hdst[pbA] = o;
        o.x = v10; o.y = v11; *(float2*)&hdst[pbB] = o;

        if (step + 1 < S_) {
            // prefetch next P (independent of recurrence) before the spin
            const size_t po = (size_t)(step + 1) * pstride;
            pPA = *(const u64*)&g_P[pbA + po];
            pPB = *(const u64*)&g_P[pbB + po];

            __syncthreads();          // STGs issued + As reads done
            if (t == 0) {
                asm volatile("red.release.gpu.add.u32 [%0], 1;" :: "l"(bar) : "memory");
                unsigned v8, target = 8u * (unsigned)(step + 1);
                do {
                    asm volatile("ld.acquire.gpu.u32 %0, [%1];" : "=r"(v8) : "l"(bar) : "memory");
                } while (v8 < target);
            }
            __syncthreads();
        }
        cur ^= 1;
    }

    const float inv = 1.0f / (float)S_;
    float2 q;
    q.x = ps.x * inv; q.y = ps.y * inv; *(float2*)&g_pool[pbA] = q;
    q.x = ps.z * inv; q.y = ps.w * inv; *(float2*)&g_pool[pbB] = q;
}

// ============================================================================
// Kernel C: out = pooled @ Wfc + bfc
// ============================================================================
__global__ __launch_bounds__(128) void fc_kernel(const float* __restrict__ Wfc,
                                                 const float* __restrict__ bfc,
                                                 float* __restrict__ out)
{
    const int b = blockIdx.x;
    const int t = threadIdx.x;
    float s0 = 0, s1 = 0, s2 = 0, s3 = 0;
    const float* pr = &g_pool[(size_t)b * H_];
    for (int k = t; k < H_; k += 128) {
        float v = pr[k];
        float4 wv = *(const float4*)&Wfc[k * 4];
        s0 += v * wv.x; s1 += v * wv.y; s2 += v * wv.z; s3 += v * wv.w;
    }
#pragma unroll
    for (int o = 16; o > 0; o >>= 1) {
        s0 += __shfl_down_sync(0xffffffffu, s0, o);
        s1 += __shfl_down_sync(0xffffffffu, s1, o);
        s2 += __shfl_down_sync(0xffffffffu, s2, o);
        s3 += __shfl_down_sync(0xffffffffu, s3, o);
    }
    __shared__ float red[4][4];
    if ((t & 31) == 0) {
        int wrp = t >> 5;
        red[wrp][0] = s0; red[wrp][1] = s1; red[wrp][2] = s2; red[wrp][3] = s3;
    }
    __syncthreads();
    if (t < 4) {
        out[b * 4 + t] = red[0][t] + red[1][t] + red[2][t] + red[3][t] + bfc[t];
    }
}

// ============================================================================
extern "C" void kernel_launch(void* const* d_in, const int* in_sizes, int n_in,
                              void* d_out, int out_size)
{
    const int*   x   = (const int*)d_in[0];
    const float* emb = (const float*)d_in[1];
    const float* Wxh = (const float*)d_in[2];
    const float* bxh = (const float*)d_in[3];
    const float* Whh = (const float*)d_in[4];
    const float* bhh = (const float*)d_in[5];
    const float* Wfc = (const float*)d_in[6];
    const float* bfc = (const float*)d_in[7];
    float* out = (float*)d_out;

    void *hAddr = nullptr, *barAddr = nullptr;
    cudaGetSymbolAddress(&hAddr, g_h);
    cudaGetSymbolAddress(&barAddr, g_bars);
    cudaMemsetAsync(hAddr, 0, sizeof(float) * 2 * B_ * H_);
    cudaMemsetAsync(barAddr, 0, sizeof(unsigned) * 16);

    cudaFuncSetAttribute(precompute_kernel, cudaFuncAttributeMaxDynamicSharedMemorySize, PC_SMEM);
    cudaFuncSetAttribute(rnn_kernel, cudaFuncAttributeMaxDynamicSharedMemorySize, RNN_SMEM);

    precompute_kernel<<<dim3(4, 800), 256, PC_SMEM>>>(x, emb, Wxh, bxh, bhh);
    rnn_kernel<<<128, 256, RNN_SMEM>>>(Whh);
    fc_kernel<<<B_, 128>>>(Wfc, bfc, out);
}